// round 17
// baseline (speedup 1.0000x reference)
#include <cuda_runtime.h>

// AlarmworkRNN collapsed to a vector RNN (only sequence row 2047 matters).
// Round 17: R16 scaffold with Phase B restructured to broadcast-lane GEMV
// (R3-proven): warp w covers K-slice [w*64,(w+1)*64) for ALL 16 outputs
// (lane = output*2 + half), cutting Phase-B crossbar traffic ~8x.
// Phase C: warp 0 reduces partials, applies tanh, publishes all 16 state
// values (z2-hold registers live in warp-0 lanes 8-15). Odd-step out-GEMVs
// run in warps 1-4 concurrent with phase C.

#define GRID  128
#define BLOCK 512
#define NSTEP 256

__device__ unsigned g_arrive;
__device__ float2 g_z[2][1024];           // parity-buffered {z1, z2}
__device__ float g_U[2][NSTEP][1024];     // u1/u2 per step (bias folded)

__device__ __forceinline__ void arrive_release(unsigned* p) {
    asm volatile("red.release.gpu.global.add.u32 [%0], %1;"
                 :: "l"(p), "r"(1u) : "memory");
}
__device__ __forceinline__ unsigned ld_acquire_gpu(unsigned* p) {
    unsigned v;
    asm volatile("ld.acquire.gpu.global.u32 %0, [%1];"
                 : "=r"(v) : "l"(p) : "memory");
    return v;
}
__device__ __forceinline__ float4 ldcg4(const float4* p) {
    float4 u;
    asm volatile("ld.global.cg.v4.f32 {%0,%1,%2,%3}, [%4];"
                 : "=f"(u.x), "=f"(u.y), "=f"(u.z), "=f"(u.w)
                 : "l"(p) : "memory");
    return u;
}

// ---- k1: U[m][t][j] = x[t,2047,:] @ W_in_m[:,j] + b_m[j] ----
// grid 512, 4 steps/block (R16-proven); block 0 folds init.
__global__ __launch_bounds__(256)
void u_kernel(const float* __restrict__ x,
              const float* __restrict__ W_in1, const float* __restrict__ b_in1,
              const float* __restrict__ W_in2, const float* __restrict__ b_in2)
{
    __shared__ float xs[4][256];
    const int b   = blockIdx.x;
    const int tid = threadIdx.x;

    if (b == 0) {
        if (tid == 0) g_arrive = 0u;
        for (int idx = tid; idx < 1024; idx += 256)
            g_z[0][idx] = make_float2(0.0f, 0.0f);
    }

    const int m   = b >> 8;
    const int jt  = (b >> 6) & 3;
    const int t0  = (b & 63) * 4;
    const float* W  = m ? W_in2 : W_in1;
    const float* bi = m ? b_in2 : b_in1;

    for (int i = tid; i < 4 * 256; i += 256) {
        int tr = i >> 8, k = i & 255;
        xs[tr][k] = x[((size_t)(t0 + tr) * 2048 + 2047) * 256 + k];
    }
    __syncthreads();

    const int j = jt * 256 + tid;
    float acc[4];
    const float bj = bi[j];
    #pragma unroll
    for (int r = 0; r < 4; r++) acc[r] = bj;
    #pragma unroll 8
    for (int k = 0; k < 256; k++) {
        float w = W[k * 1024 + j];
        #pragma unroll
        for (int r = 0; r < 4; r++) acc[r] += xs[r][k] * w;
    }
    #pragma unroll
    for (int r = 0; r < 4; r++) g_U[m][t0 + r][j] = acc[r];
}

// ---- k2: persistent recurrence + in-loop out ----
__global__ __launch_bounds__(BLOCK, 1)
void rnn_main_kernel(const float* __restrict__ W_rec1,
                     const float* __restrict__ W_rec2,
                     const float* __restrict__ W_out,
                     const float* __restrict__ b_out,
                     float* __restrict__ out)
{
    extern __shared__ float sm[];
    float* e1     = sm;                 // [1024]   z1 + z2
    float* e2     = e1 + 1024;          // [1024]   z2
    float* z1s    = e2 + 1024;          // [2][1024] z1 snapshots by parity
    float* wout_s = z1s + 2048;         // [2][1024] this CTA's W_out columns
    float* redp   = wout_s + 2048;      // [16*17]  partials, padded
    float* stage  = redp + 272;         // [1024*9] weight staging (preload only)

    const int tid  = threadIdx.x;
    const int warp = tid >> 5;
    const int lane = tid & 31;
    const int j0   = blockIdx.x * 8;
    const int o0   = blockIdx.x * 2;
    const int o_l  = lane >> 1;         // output index 0..15 (0-7: z1, 8-15: z2)
    const int h_l  = lane & 1;          // half of the 64-elem K-slice

    // ---- preload recurrent weights: lane (o,h) of warp w holds
    //      W_sel[w*64 + h*32 + s][j0 + (o&7)], s = 0..31 ----
    float wreg[32];
    for (int round = 0; round < 2; round++) {
        const float* W = round ? W_rec2 : W_rec1;
        for (int idx = tid; idx < 1024 * 8; idx += BLOCK) {
            int k = idx >> 3, c = idx & 7;
            stage[k * 9 + c] = W[k * 1024 + j0 + c];
        }
        __syncthreads();
        if ((o_l < 8) == (round == 0)) {
            const int kbase = warp * 64 + h_l * 32;
            #pragma unroll
            for (int s = 0; s < 32; s++)
                wreg[s] = stage[(kbase + s) * 9 + (o_l & 7)];
        }
        __syncthreads();
    }

    // preload this CTA's two W_out columns into SMEM
    for (int idx = tid; idx < 2048; idx += BLOCK) {
        int jj = idx >> 1, c = idx & 1;
        wout_s[c * 1024 + jj] = W_out[jj * 256 + o0 + c];
    }
    // out warps 1-4: t_sel = (warp-1)>>1, o_sel = (warp-1)&1
    const float obia = (warp >= 1 && warp <= 4) ? b_out[o0 + ((warp - 1) & 1)] : 0.0f;
    __syncthreads();

    float z2hold = 0.0f;                // warp-0 lanes 8-15: held z2 value

    for (int i = 0; i < NSTEP; i++) {
        const int par = i & 1;
        const int pw  = par ^ 1;

        // phase-C warp's u prefetch (issued early, hidden under Phase A)
        float u = 0.0f;
        if (warp == 0 && lane < 16)
            u = g_U[lane >> 3][i][j0 + (lane & 7)];

        // Phase A: stage state into SMEM (+ z1 snapshot for out-GEMV)
        {
            float4 q = ldcg4(((const float4*)g_z[par]) + tid); // {z1a,z2a,z1b,z2b}
            ((float2*)e1)[tid]  = make_float2(q.x + q.y, q.z + q.w);
            ((float2*)e2)[tid]  = make_float2(q.y, q.w);
            ((float2*)(z1s + par * 1024))[tid] = make_float2(q.x, q.z);
        }
        __syncthreads();

        // Phase B: broadcast-lane partial dots.
        // Warp w covers K in [w*64, w*64+64); lane handles output o_l, half h_l.
        {
            const float* base = ((o_l < 8) ? e1 : e2) + warp * 64 + h_l * 32;
            const float4* eb  = (const float4*)base;
            float a0 = 0.0f, a1 = 0.0f;
            #pragma unroll
            for (int c = 0; c < 8; c++) {
                float4 q = eb[c];
                a0 += wreg[4*c+0] * q.x + wreg[4*c+1] * q.y;
                a1 += wreg[4*c+2] * q.z + wreg[4*c+3] * q.w;
            }
            float acc = a0 + a1;
            acc += __shfl_xor_sync(0xffffffffu, acc, 1);   // combine halves
            if (h_l == 0) redp[o_l * 17 + warp] = acc;
        }
        __syncthreads();

        // Phase C (warp 0): reduce 16 partials per output, tanh, publish.
        // Concurrent: odd steps, warps 1-4 compute out[i-2], out[i-1].
        if (warp == 0) {
            if (lane < 16) {
                float s2 = 0.0f;
                #pragma unroll
                for (int w = 0; w < 16; w++) s2 += redp[lane * 17 + w];
                if (lane < 8) {
                    ((float*)&g_z[pw][j0 + lane])[0] = tanhf(s2 + u);
                } else {
                    if ((i & 1) == 0) z2hold = tanhf(s2 + u);
                    ((float*)&g_z[pw][j0 + lane - 8])[1] = z2hold;
                }
            }
        } else if ((i & 1) == 1 && warp <= 4) {
            const int t_sel = (warp - 1) >> 1;    // 0: out[i-2], 1: out[i-1]
            const int o_sel = (warp - 1) & 1;
            if (!(t_sel == 0 && i == 1)) {
                const float4* wv = (const float4*)(wout_s + o_sel * 1024);
                const float4* zv = (const float4*)(z1s + t_sel * 1024);
                float a0 = 0.0f, a1 = 0.0f;
                #pragma unroll
                for (int c = 0; c < 8; c++) {
                    float4 wq = wv[c * 32 + lane];
                    float4 zq = zv[c * 32 + lane];
                    a0 += wq.x * zq.x + wq.y * zq.y;
                    a1 += wq.z * zq.z + wq.w * zq.w;
                }
                float acc = a0 + a1;
                #pragma unroll
                for (int off = 16; off; off >>= 1)
                    acc += __shfl_xor_sync(0xffffffffu, acc, off);
                if (lane == 0)
                    out[(size_t)(i - 2 + t_sel) * 256 + o0 + o_sel] =
                        tanhf(acc + obia);
            }
        }
        __syncthreads();   // all publishes issued before arrive

        if (i + 1 < NSTEP) {
            if (tid == 0) {
                arrive_release(&g_arrive);
                const unsigned target = (unsigned)(i + 1) * GRID;
                while (ld_acquire_gpu(&g_arrive) < target) { }
            }
            __syncthreads();
        }
    }

    // Tail: final barrier round, then out[255] from z1(256)
    if (tid == 0) {
        arrive_release(&g_arrive);
        const unsigned target = (unsigned)NSTEP * GRID;
        while (ld_acquire_gpu(&g_arrive) < target) { }
    }
    __syncthreads();
    {
        float4 q = ldcg4(((const float4*)g_z[0]) + tid);   // z(256) lives in g_z[0]
        ((float2*)z1s)[tid] = make_float2(q.x, q.z);
        __syncthreads();
        if (warp == 1 || warp == 2) {          // cols o0+0, o0+1
            const int o_sel = warp - 1;
            const float4* wv = (const float4*)(wout_s + o_sel * 1024);
            const float4* zv = (const float4*)z1s;
            float a0 = 0.0f, a1 = 0.0f;
            #pragma unroll
            for (int c = 0; c < 8; c++) {
                float4 wq = wv[c * 32 + lane];
                float4 zq = zv[c * 32 + lane];
                a0 += wq.x * zq.x + wq.y * zq.y;
                a1 += wq.z * zq.z + wq.w * zq.w;
            }
            float acc = a0 + a1;
            #pragma unroll
            for (int off = 16; off; off >>= 1)
                acc += __shfl_xor_sync(0xffffffffu, acc, off);
            if (lane == 0)
                out[(size_t)255 * 256 + o0 + o_sel] = tanhf(acc + b_out[o0 + o_sel]);
        }
    }
}

extern "C" void kernel_launch(void* const* d_in, const int* in_sizes, int n_in,
                              void* d_out, int out_size) {
    (void)in_sizes; (void)n_in; (void)out_size;
    const float* x      = (const float*)d_in[0];
    const float* W_in1  = (const float*)d_in[1];
    const float* b_in1  = (const float*)d_in[2];
    const float* W_rec1 = (const float*)d_in[3];
    const float* W_in2  = (const float*)d_in[4];
    const float* b_in2  = (const float*)d_in[5];
    const float* W_rec2 = (const float*)d_in[6];
    const float* W_out  = (const float*)d_in[7];
    const float* b_out  = (const float*)d_in[8];
    float* out = (float*)d_out;

    const size_t smem_bytes =
        (size_t)(1024 + 1024 + 2048 + 2048 + 272 + 1024 * 9) * sizeof(float); // 62.5 KB
    cudaFuncSetAttribute(rnn_main_kernel,
                         cudaFuncAttributeMaxDynamicSharedMemorySize,
                         (int)smem_bytes);

    u_kernel<<<512, 256>>>(x, W_in1, b_in1, W_in2, b_in2);
    rnn_main_kernel<<<GRID, BLOCK, smem_bytes>>>(W_rec1, W_rec2, W_out, b_out, out);
}